// round 13
// baseline (speedup 1.0000x reference)
#include <cuda_runtime.h>
#include <cuda_bf16.h>
#include <cuda_fp16.h>
#include <stdint.h>
#include <math.h>

#define NS 16384
#define ND 2048
#define NC 1000
#define NCP 1024

#define MARGIN 1.5f

// GEMM tiling: 128x128 block, 8 warps (4x2), warp tile 32x64, 2 CTAs/SM
#define BM 128
#define BN 128
#define BK 64                  // K per chunk: 128 bytes/row (SW128 atom)
#define KCHUNKS (ND / BK)      // 32
#define STAGES 3
#define A_TILE_BYTES (BM * BK * 2)   // 16384
#define B_TILE_BYTES (BN * BK * 2)   // 16384
#define STAGE_BYTES (A_TILE_BYTES + B_TILE_BYTES)  // 32768
#define SMEM_TOTAL (STAGES * STAGE_BYTES + 1024)

#define NBN (NCP / BN)         // 8 partials per row

// out-zeroing slice per GEMM CTA: NS*NC/1024 = 16000 floats = 4000 float4
#define ZERO_F4_PER_CTA 4000

// ---------------- scratch (static device globals) ---------------------------
__device__ __nv_bfloat16 g_xb[(size_t)NS * ND];    // tiled: [bm][kt][128x64 SW128]
__device__ __nv_bfloat16 g_mb[(size_t)NCP * ND];   // tiled: [bn][kt][128x64 SW128]
__device__ __half        g_scores[(size_t)NS * NCP];
__device__ float         g_pmax[(size_t)NS * NBN];
__device__ float         g_psnd[(size_t)NS * NBN];
__device__ int           g_pidx[(size_t)NS * NBN];
__device__ float         g_thr[NS];
__device__ int           g_refine_list[NS];
__device__ int           g_refine_cnt;

// ---------------- helpers ----------------------------------------------------
__device__ __forceinline__ uint32_t smem_u32(const void* p) {
    return (uint32_t)__cvta_generic_to_shared(p);
}
__host__ __device__ __forceinline__ uint32_t sw128(uint32_t off) {
    return off ^ ((off >> 3) & 0x70);
}
__device__ __forceinline__ void cp16(uint32_t dst, const void* src) {
    asm volatile("cp.async.cg.shared.global [%0], [%1], 16;"
                 :: "r"(dst), "l"(src) : "memory");
}
__device__ __forceinline__ void cp_commit() {
    asm volatile("cp.async.commit_group;" ::: "memory");
}
template <int N>
__device__ __forceinline__ void cp_wait() {
    asm volatile("cp.async.wait_group %0;" :: "n"(N) : "memory");
}
__device__ __forceinline__ void ldsm_x4(uint32_t& r0, uint32_t& r1, uint32_t& r2,
                                        uint32_t& r3, uint32_t addr) {
    asm volatile("ldmatrix.sync.aligned.m8n8.x4.shared.b16 {%0,%1,%2,%3}, [%4];\n"
                 : "=r"(r0), "=r"(r1), "=r"(r2), "=r"(r3) : "r"(addr));
}
__device__ __forceinline__ void mma_bf16(float* c, const uint32_t* a, const uint32_t* b) {
    asm volatile(
        "mma.sync.aligned.m16n8k16.row.col.f32.bf16.bf16.f32 "
        "{%0,%1,%2,%3}, {%4,%5,%6,%7}, {%8,%9}, {%0,%1,%2,%3};\n"
        : "+f"(c[0]), "+f"(c[1]), "+f"(c[2]), "+f"(c[3])
        : "r"(a[0]), "r"(a[1]), "r"(a[2]), "r"(a[3]), "r"(b[0]), "r"(b[1]));
}
// combine (max, idx, second) partials; prefer larger val, then smaller idx
__device__ __forceinline__ void comb(float& m, int& id, float& s,
                                     float om, int oid, float os) {
    if (om > m || (om == m && oid < id)) {
        s = fmaxf(m, os); m = om; id = oid;
    } else {
        s = fmaxf(s, om);
    }
}

// ---------------- merged convert kernel (x then means) ----------------------
#define XCHUNKS (NS * (size_t)ND / 8)     // 4,194,304
#define MCHUNKS ((size_t)NCP * ND / 8)    // 524,288

__global__ __launch_bounds__(256) void cvt_all_kernel(const float4* __restrict__ x,
                                                      const float4* __restrict__ m) {
    size_t g = (size_t)blockIdx.x * 256 + threadIdx.x;
    if (g < XCHUNKS) {
        uint32_t gg = (uint32_t)g;
        uint32_t tile = gg >> 10;                  // [bm(128)][kt(32)]
        uint32_t w    = gg & 1023;
        uint32_t tm = tile >> 5, tk = tile & 31;
        uint32_t r  = w >> 3, cgrp = w & 7;
        uint32_t row = tm * 128 + r;
        size_t src = (size_t)row * 512 + tk * 16 + cgrp * 2;
        float4 v0 = x[src];
        float4 v1 = x[src + 1];
        __nv_bfloat162 b0 = __floats2bfloat162_rn(v0.x, v0.y);
        __nv_bfloat162 b1 = __floats2bfloat162_rn(v0.z, v0.w);
        __nv_bfloat162 b2 = __floats2bfloat162_rn(v1.x, v1.y);
        __nv_bfloat162 b3 = __floats2bfloat162_rn(v1.z, v1.w);
        uint4 q;
        q.x = *reinterpret_cast<uint32_t*>(&b0);
        q.y = *reinterpret_cast<uint32_t*>(&b1);
        q.z = *reinterpret_cast<uint32_t*>(&b2);
        q.w = *reinterpret_cast<uint32_t*>(&b3);
        *reinterpret_cast<uint4*>((char*)g_xb + (size_t)tile * A_TILE_BYTES +
                                  sw128(w * 16)) = q;
        if (gg == 0) g_refine_cnt = 0;
    } else {
        uint32_t gg = (uint32_t)(g - XCHUNKS);
        uint32_t tile = gg >> 10;                  // [bn(8)][kt(32)]
        uint32_t w    = gg & 1023;
        uint32_t tb = tile >> 5, tk = tile & 31;
        uint32_t r  = w >> 3, cgrp = w & 7;
        uint32_t row = tb * 128 + r;
        float4 v0 = make_float4(0.f, 0.f, 0.f, 0.f), v1 = v0;
        if (row < NC) {
            size_t src = (size_t)row * 512 + tk * 16 + cgrp * 2;
            v0 = m[src];
            v1 = m[src + 1];
        }
        __nv_bfloat162 b0 = __floats2bfloat162_rn(v0.x, v0.y);
        __nv_bfloat162 b1 = __floats2bfloat162_rn(v0.z, v0.w);
        __nv_bfloat162 b2 = __floats2bfloat162_rn(v1.x, v1.y);
        __nv_bfloat162 b3 = __floats2bfloat162_rn(v1.z, v1.w);
        uint4 q;
        q.x = *reinterpret_cast<uint32_t*>(&b0);
        q.y = *reinterpret_cast<uint32_t*>(&b1);
        q.z = *reinterpret_cast<uint32_t*>(&b2);
        q.w = *reinterpret_cast<uint32_t*>(&b3);
        *reinterpret_cast<uint4*>((char*)g_mb + (size_t)tile * B_TILE_BYTES +
                                  sw128(w * 16)) = q;
    }
}

// ---------------- GEMM: 128x128 block, 8 warps 4x2, warp 32x64 --------------
// Cross-chunk fragment prefetch + fused output zeroing in the prologue.
__global__ __launch_bounds__(256, 2) void gemm_mma8_kernel(float4* __restrict__ out) {
    extern __shared__ char smem[];
    const uint32_t sb = (smem_u32(smem) + 1023u) & ~1023u;

    const int tid  = threadIdx.x;
    const int lane = tid & 31;
    const int wid  = tid >> 5;
    const int wm   = wid >> 1;   // 0..3 -> 32-row slab
    const int wn   = wid & 1;    // 0..1 -> 64-col slab
    const int bn   = blockIdx.x; // 0..7
    const int bm   = blockIdx.y; // 0..127

    const char* gA = (const char*)g_xb + (size_t)bm * KCHUNKS * A_TILE_BYTES;
    const char* gB = (const char*)g_mb + (size_t)bn * KCHUNKS * B_TILE_BYTES;

    auto load_stage = [&](int s, int kt) {
        uint32_t Ad = sb + s * STAGE_BYTES;
        const char* Asrc = gA + (size_t)kt * A_TILE_BYTES;
        #pragma unroll
        for (int i = 0; i < 4; i++) {
            int ch = tid + i * 256;
            cp16(Ad + ch * 16, Asrc + ch * 16);
        }
        uint32_t Bd = Ad + A_TILE_BYTES;
        const char* Bsrc = gB + (size_t)kt * B_TILE_BYTES;
        #pragma unroll
        for (int i = 0; i < 4; i++) {
            int ch = tid + i * 256;
            cp16(Bd + ch * 16, Bsrc + ch * 16);
        }
    };

    float acc[2][8][4];
    #pragma unroll
    for (int i = 0; i < 2; i++)
        #pragma unroll
        for (int j = 0; j < 8; j++)
            #pragma unroll
            for (int k = 0; k < 4; k++) acc[i][j][k] = 0.f;

    load_stage(0, 0); cp_commit();
    load_stage(1, 1); cp_commit();

    // fused zero of this CTA's out slice (overlaps the cp.async prefetch)
    {
        const int cta = bm * NBN + bn;               // 0..1023
        float4* z = out + (size_t)cta * ZERO_F4_PER_CTA;
        const float4 zf = make_float4(0.f, 0.f, 0.f, 0.f);
        #pragma unroll
        for (int i = 0; i < 16; i++) {
            int ch = tid + i * 256;
            if (ch < ZERO_F4_PER_CTA) z[ch] = zf;
        }
    }

    const int a_row = wm * 32 + (lane & 15);
    const int a_kb  = ((lane >> 4) << 3) * 2;
    const int b_row = wn * 64 + ((lane >> 4) << 3) + (lane & 7);
    const int b_kb  = (((lane >> 3) & 1) << 3) * 2;

    uint32_t afr[2][2][4];
    uint32_t bfr[2][8][2];

    auto frag_load = [&](uint32_t Ab, uint32_t Bb, int ks, int buf) {
        #pragma unroll
        for (int mt = 0; mt < 2; mt++) {
            uint32_t off = (uint32_t)((a_row + mt * 16) * 128 + ks * 32 + a_kb);
            ldsm_x4(afr[buf][mt][0], afr[buf][mt][1], afr[buf][mt][2],
                    afr[buf][mt][3], Ab + sw128(off));
        }
        #pragma unroll
        for (int nb = 0; nb < 4; nb++) {
            uint32_t off = (uint32_t)((b_row + nb * 16) * 128 + ks * 32 + b_kb);
            uint32_t r0, r1, r2, r3;
            ldsm_x4(r0, r1, r2, r3, Bb + sw128(off));
            bfr[buf][nb * 2 + 0][0] = r0; bfr[buf][nb * 2 + 0][1] = r1;
            bfr[buf][nb * 2 + 1][0] = r2; bfr[buf][nb * 2 + 1][1] = r3;
        }
    };

    // stage 0 ready for everyone, then preload (kt=0, ks=0) fragments
    cp_wait<1>();
    __syncthreads();
    frag_load(sb, sb + A_TILE_BYTES, 0, 0);

    for (int kt = 0; kt < KCHUNKS; kt++) {
        if (kt + 2 < KCHUNKS) { load_stage((kt + 2) % STAGES, kt + 2); cp_commit(); }

        const uint32_t Ab  = sb + (kt % STAGES) * STAGE_BYTES;
        const uint32_t Bb  = Ab + A_TILE_BYTES;
        const uint32_t Abn = sb + ((kt + 1) % STAGES) * STAGE_BYTES;
        const uint32_t Bbn = Abn + A_TILE_BYTES;

        #pragma unroll
        for (int ks = 0; ks < 4; ks++) {
            const int cur = ks & 1;
            if (ks < 3) {
                frag_load(Ab, Bb, ks + 1, cur ^ 1);
            } else if (kt + 1 < KCHUNKS) {
                if (kt == KCHUNKS - 2) cp_wait<0>(); else cp_wait<1>();
                __syncthreads();   // make all threads' stage-(kt+1) copies visible
                frag_load(Abn, Bbn, 0, cur ^ 1);
            }
            #pragma unroll
            for (int mt = 0; mt < 2; mt++)
                #pragma unroll
                for (int nt = 0; nt < 8; nt++)
                    mma_bf16(acc[mt][nt], afr[cur][mt], bfr[cur][nt]);
        }
    }

    // ---------------- epilogue: store fp16 scores + per-row (max,idx,second) -
    #pragma unroll
    for (int mt = 0; mt < 2; mt++) {
        #pragma unroll
        for (int nt = 0; nt < 8; nt++) {
            int row = bm * BM + wm * 32 + mt * 16 + (lane >> 2);
            int col = bn * BN + wn * 64 + nt * 8 + ((lane & 3) << 1);
            *reinterpret_cast<__half2*>(&g_scores[(size_t)row * NCP + col]) =
                __floats2half2_rn(acc[mt][nt][0], acc[mt][nt][1]);
            *reinterpret_cast<__half2*>(&g_scores[(size_t)(row + 8) * NCP + col]) =
                __floats2half2_rn(acc[mt][nt][2], acc[mt][nt][3]);
        }
    }

    __syncthreads();   // stage buffers dead; reuse smem for partial reduction
    float* pm = reinterpret_cast<float*>(smem);        // [2][128]
    float* ps = pm + 256;                              // [2][128]
    int*   pi = reinterpret_cast<int*>(ps + 256);      // [2][128]

    const int cbase = bn * BN + wn * 64 + ((lane & 3) << 1);
    #pragma unroll
    for (int mt = 0; mt < 2; mt++) {
        #pragma unroll
        for (int h = 0; h < 2; h++) {
            float m = -INFINITY, s = -INFINITY;
            int   id = 0;
            #pragma unroll
            for (int nt = 0; nt < 8; nt++) {
                #pragma unroll
                for (int e = 0; e < 2; e++) {
                    int   col = cbase + nt * 8 + e;
                    float v   = acc[mt][nt][h * 2 + e];
                    if (col >= NC) v = -INFINITY;
                    if (v > m) { s = m; m = v; id = col; }
                    else if (v > s) s = v;
                }
            }
            #pragma unroll
            for (int x = 1; x <= 2; x <<= 1) {
                float om = __shfl_xor_sync(0xffffffffu, m, x);
                int   oi = __shfl_xor_sync(0xffffffffu, id, x);
                float os = __shfl_xor_sync(0xffffffffu, s, x);
                comb(m, id, s, om, oi, os);
            }
            if ((lane & 3) == 0) {
                int rl = wm * 32 + mt * 16 + h * 8 + (lane >> 2);
                pm[wn * 128 + rl] = m;
                ps[wn * 128 + rl] = s;
                pi[wn * 128 + rl] = id;
            }
        }
    }
    __syncthreads();

    if (tid < 128) {
        float m = pm[tid];      int id = pi[tid];      float s = ps[tid];
        comb(m, id, s, pm[128 + tid], pi[128 + tid], ps[128 + tid]);
        size_t o = (size_t)(bm * BM + tid) * NBN + bn;
        g_pmax[o] = m; g_psnd[o] = s; g_pidx[o] = id;
    }
}

// ---------------- combine partials -> thr + write unflagged one-hot ---------
__global__ __launch_bounds__(256) void argmax_combine_kernel(float* __restrict__ out) {
    const int s = blockIdx.x * 256 + threadIdx.x;
    if (s >= NS) return;
    const size_t base = (size_t)s * NBN;
    float m = g_pmax[base];  int id = g_pidx[base];  float snd = g_psnd[base];
    #pragma unroll
    for (int p = 1; p < NBN; p++)
        comb(m, id, snd, g_pmax[base + p], g_pidx[base + p], g_psnd[base + p]);

    const float thr = m - MARGIN;
    if (snd >= thr) {
        g_thr[s] = thr;
        int p = atomicAdd(&g_refine_cnt, 1);
        g_refine_list[p] = s;
    } else {
        out[(size_t)s * NC + id] = 1.0f;   // no competitor within margin
    }
}

// ---------------- warp-per-sample exact fp64 refinement ---------------------
// One warp per flagged sample: ballot-scan candidates, warp-parallel fp64 dot,
// no block barriers, no smem. Candidates visited in ascending class order;
// strict > keeps the smaller class on ties.
__global__ __launch_bounds__(256) void refine_warp_kernel(
    const float* __restrict__ x, const float* __restrict__ means,
    float* __restrict__ out) {
    const int lane = threadIdx.x & 31;
    const int gw   = (blockIdx.x * 256 + threadIdx.x) >> 5;
    const int nw   = (gridDim.x * 256) >> 5;

    const int total = g_refine_cnt;
    for (int r = gw; r < total; r += nw) {
        const int    s    = g_refine_list[r];
        const float  thr  = g_thr[s];
        const __half* srow = g_scores + (size_t)s * NCP;
        const float* xr   = x + (size_t)s * ND;

        double bestv = -1e300;
        int    bestc = 1 << 30;

        #pragma unroll 4
        for (int c = 0; c < 32; c++) {
            int   j = c * 32 + lane;
            float v = (j < NC) ? __half2float(srow[j]) : -1e30f;
            unsigned mask = __ballot_sync(0xffffffffu, v >= thr);
            while (mask) {
                int b = __ffs(mask) - 1;
                mask &= mask - 1;
                const int cls = c * 32 + b;
                const float* mr = means + (size_t)cls * ND;
                double a0 = 0.0, a1 = 0.0, a2 = 0.0, a3 = 0.0;
                #pragma unroll
                for (int t = 0; t < 64; t += 4) {
                    int e = lane + 32 * t;
                    a0 += (double)xr[e]        * (double)mr[e];
                    a1 += (double)xr[e + 32]   * (double)mr[e + 32];
                    a2 += (double)xr[e + 64]   * (double)mr[e + 64];
                    a3 += (double)xr[e + 96]   * (double)mr[e + 96];
                }
                double tot = (a0 + a1) + (a2 + a3);
                #pragma unroll
                for (int o = 16; o > 0; o >>= 1)
                    tot += __shfl_down_sync(0xffffffffu, tot, o);
                tot = __shfl_sync(0xffffffffu, tot, 0);
                if (tot > bestv) { bestv = tot; bestc = cls; }
            }
        }
        if (lane == 0) out[(size_t)s * NC + bestc] = 1.0f;
    }
}

// ---------------- launch ----------------------------------------------------
extern "C" void kernel_launch(void* const* d_in, const int* in_sizes, int n_in,
                              void* d_out, int out_size) {
    const float* x     = (const float*)d_in[0];
    const float* means = (const float*)d_in[1];
    float* out = (float*)d_out;

    cudaFuncSetAttribute(gemm_mma8_kernel,
                         cudaFuncAttributeMaxDynamicSharedMemorySize, SMEM_TOTAL);

    const int cvt_blocks = (int)((XCHUNKS + MCHUNKS) / 256);
    cvt_all_kernel<<<cvt_blocks, 256>>>(                          // launch 1
        reinterpret_cast<const float4*>(x),
        reinterpret_cast<const float4*>(means));
    gemm_mma8_kernel<<<dim3(NCP / BN, NS / BM), 256, SMEM_TOTAL>>>( // launch 2
        reinterpret_cast<float4*>(out));
    argmax_combine_kernel<<<NS / 256, 256>>>(out);                // launch 3
    refine_warp_kernel<<<512, 256>>>(x, means, out);              // launch 4 (ncu)
}

// round 14
// speedup vs baseline: 1.0562x; 1.0562x over previous
#include <cuda_runtime.h>
#include <cuda_bf16.h>
#include <cuda_fp16.h>
#include <stdint.h>
#include <math.h>

#define NS 16384
#define ND 2048
#define NC 1000
#define NCP 1024

#define MARGIN 1.5f

// GEMM tiling: 128x128 block, 8 warps (4x2), warp tile 32x64, 2 CTAs/SM
#define BM 128
#define BN 128
#define BK 64                  // K per chunk: 128 bytes/row (SW128 atom)
#define KCHUNKS (ND / BK)      // 32
#define STAGES 3
#define A_TILE_BYTES (BM * BK * 2)   // 16384
#define B_TILE_BYTES (BN * BK * 2)   // 16384
#define STAGE_BYTES (A_TILE_BYTES + B_TILE_BYTES)  // 32768
#define SMEM_TOTAL (STAGES * STAGE_BYTES + 1024)

#define NBN (NCP / BN)         // 8 partials per row

// out-zeroing slice per GEMM CTA: NS*NC/1024 = 16000 floats = 4000 float4
#define ZERO_F4_PER_CTA 4000

// ---------------- scratch (static device globals) ---------------------------
__device__ __nv_bfloat16 g_xb[(size_t)NS * ND];    // tiled: [bm][kt][128x64 SW128]
__device__ __nv_bfloat16 g_mb[(size_t)NCP * ND];   // tiled: [bn][kt][128x64 SW128]
__device__ __half        g_scores[(size_t)NS * NCP];
__device__ float         g_pmax[(size_t)NS * NBN];
__device__ float         g_psnd[(size_t)NS * NBN];
__device__ int           g_pidx[(size_t)NS * NBN];
__device__ float         g_thr[NS];
__device__ int           g_refine_list[NS];
__device__ int           g_refine_cnt;

// ---------------- helpers ----------------------------------------------------
__device__ __forceinline__ uint32_t smem_u32(const void* p) {
    return (uint32_t)__cvta_generic_to_shared(p);
}
__host__ __device__ __forceinline__ uint32_t sw128(uint32_t off) {
    return off ^ ((off >> 3) & 0x70);
}
__device__ __forceinline__ void cp16(uint32_t dst, const void* src) {
    asm volatile("cp.async.cg.shared.global [%0], [%1], 16;"
                 :: "r"(dst), "l"(src) : "memory");
}
__device__ __forceinline__ void cp_commit() {
    asm volatile("cp.async.commit_group;" ::: "memory");
}
template <int N>
__device__ __forceinline__ void cp_wait() {
    asm volatile("cp.async.wait_group %0;" :: "n"(N) : "memory");
}
__device__ __forceinline__ void ldsm_x4(uint32_t& r0, uint32_t& r1, uint32_t& r2,
                                        uint32_t& r3, uint32_t addr) {
    asm volatile("ldmatrix.sync.aligned.m8n8.x4.shared.b16 {%0,%1,%2,%3}, [%4];\n"
                 : "=r"(r0), "=r"(r1), "=r"(r2), "=r"(r3) : "r"(addr));
}
__device__ __forceinline__ void mma_bf16(float* c, const uint32_t* a, const uint32_t* b) {
    asm volatile(
        "mma.sync.aligned.m16n8k16.row.col.f32.bf16.bf16.f32 "
        "{%0,%1,%2,%3}, {%4,%5,%6,%7}, {%8,%9}, {%0,%1,%2,%3};\n"
        : "+f"(c[0]), "+f"(c[1]), "+f"(c[2]), "+f"(c[3])
        : "r"(a[0]), "r"(a[1]), "r"(a[2]), "r"(a[3]), "r"(b[0]), "r"(b[1]));
}
// combine (max, idx, second) partials; prefer larger val, then smaller idx
__device__ __forceinline__ void comb(float& m, int& id, float& s,
                                     float om, int oid, float os) {
    if (om > m || (om == m && oid < id)) {
        s = fmaxf(m, os); m = om; id = oid;
    } else {
        s = fmaxf(s, om);
    }
}

// ---------------- merged convert kernel (x then means) ----------------------
#define XCHUNKS (NS * (size_t)ND / 8)     // 4,194,304
#define MCHUNKS ((size_t)NCP * ND / 8)    // 524,288

__global__ __launch_bounds__(256) void cvt_all_kernel(const float4* __restrict__ x,
                                                      const float4* __restrict__ m) {
    size_t g = (size_t)blockIdx.x * 256 + threadIdx.x;
    if (g < XCHUNKS) {
        uint32_t gg = (uint32_t)g;
        uint32_t tile = gg >> 10;                  // [bm(128)][kt(32)]
        uint32_t w    = gg & 1023;
        uint32_t tm = tile >> 5, tk = tile & 31;
        uint32_t r  = w >> 3, cgrp = w & 7;
        uint32_t row = tm * 128 + r;
        size_t src = (size_t)row * 512 + tk * 16 + cgrp * 2;
        float4 v0 = x[src];
        float4 v1 = x[src + 1];
        __nv_bfloat162 b0 = __floats2bfloat162_rn(v0.x, v0.y);
        __nv_bfloat162 b1 = __floats2bfloat162_rn(v0.z, v0.w);
        __nv_bfloat162 b2 = __floats2bfloat162_rn(v1.x, v1.y);
        __nv_bfloat162 b3 = __floats2bfloat162_rn(v1.z, v1.w);
        uint4 q;
        q.x = *reinterpret_cast<uint32_t*>(&b0);
        q.y = *reinterpret_cast<uint32_t*>(&b1);
        q.z = *reinterpret_cast<uint32_t*>(&b2);
        q.w = *reinterpret_cast<uint32_t*>(&b3);
        *reinterpret_cast<uint4*>((char*)g_xb + (size_t)tile * A_TILE_BYTES +
                                  sw128(w * 16)) = q;
        if (gg == 0) g_refine_cnt = 0;
    } else {
        uint32_t gg = (uint32_t)(g - XCHUNKS);
        uint32_t tile = gg >> 10;                  // [bn(8)][kt(32)]
        uint32_t w    = gg & 1023;
        uint32_t tb = tile >> 5, tk = tile & 31;
        uint32_t r  = w >> 3, cgrp = w & 7;
        uint32_t row = tb * 128 + r;
        float4 v0 = make_float4(0.f, 0.f, 0.f, 0.f), v1 = v0;
        if (row < NC) {
            size_t src = (size_t)row * 512 + tk * 16 + cgrp * 2;
            v0 = m[src];
            v1 = m[src + 1];
        }
        __nv_bfloat162 b0 = __floats2bfloat162_rn(v0.x, v0.y);
        __nv_bfloat162 b1 = __floats2bfloat162_rn(v0.z, v0.w);
        __nv_bfloat162 b2 = __floats2bfloat162_rn(v1.x, v1.y);
        __nv_bfloat162 b3 = __floats2bfloat162_rn(v1.z, v1.w);
        uint4 q;
        q.x = *reinterpret_cast<uint32_t*>(&b0);
        q.y = *reinterpret_cast<uint32_t*>(&b1);
        q.z = *reinterpret_cast<uint32_t*>(&b2);
        q.w = *reinterpret_cast<uint32_t*>(&b3);
        *reinterpret_cast<uint4*>((char*)g_mb + (size_t)tile * B_TILE_BYTES +
                                  sw128(w * 16)) = q;
    }
}

// ---------------- GEMM: 128x128 block, 8 warps 4x2, warp 32x64 --------------
// Cross-chunk fragment prefetch + fused output zeroing in the prologue.
__global__ __launch_bounds__(256, 2) void gemm_mma8_kernel(float4* __restrict__ out) {
    extern __shared__ char smem[];
    const uint32_t sb = (smem_u32(smem) + 1023u) & ~1023u;

    const int tid  = threadIdx.x;
    const int lane = tid & 31;
    const int wid  = tid >> 5;
    const int wm   = wid >> 1;   // 0..3 -> 32-row slab
    const int wn   = wid & 1;    // 0..1 -> 64-col slab
    const int bn   = blockIdx.x; // 0..7
    const int bm   = blockIdx.y; // 0..127

    const char* gA = (const char*)g_xb + (size_t)bm * KCHUNKS * A_TILE_BYTES;
    const char* gB = (const char*)g_mb + (size_t)bn * KCHUNKS * B_TILE_BYTES;

    auto load_stage = [&](int s, int kt) {
        uint32_t Ad = sb + s * STAGE_BYTES;
        const char* Asrc = gA + (size_t)kt * A_TILE_BYTES;
        #pragma unroll
        for (int i = 0; i < 4; i++) {
            int ch = tid + i * 256;
            cp16(Ad + ch * 16, Asrc + ch * 16);
        }
        uint32_t Bd = Ad + A_TILE_BYTES;
        const char* Bsrc = gB + (size_t)kt * B_TILE_BYTES;
        #pragma unroll
        for (int i = 0; i < 4; i++) {
            int ch = tid + i * 256;
            cp16(Bd + ch * 16, Bsrc + ch * 16);
        }
    };

    float acc[2][8][4];
    #pragma unroll
    for (int i = 0; i < 2; i++)
        #pragma unroll
        for (int j = 0; j < 8; j++)
            #pragma unroll
            for (int k = 0; k < 4; k++) acc[i][j][k] = 0.f;

    load_stage(0, 0); cp_commit();
    load_stage(1, 1); cp_commit();

    // fused zero of this CTA's out slice (overlaps the cp.async prefetch)
    {
        const int cta = bm * NBN + bn;               // 0..1023
        float4* z = out + (size_t)cta * ZERO_F4_PER_CTA;
        const float4 zf = make_float4(0.f, 0.f, 0.f, 0.f);
        #pragma unroll
        for (int i = 0; i < 16; i++) {
            int ch = tid + i * 256;
            if (ch < ZERO_F4_PER_CTA) z[ch] = zf;
        }
    }

    const int a_row = wm * 32 + (lane & 15);
    const int a_kb  = ((lane >> 4) << 3) * 2;
    const int b_row = wn * 64 + ((lane >> 4) << 3) + (lane & 7);
    const int b_kb  = (((lane >> 3) & 1) << 3) * 2;

    uint32_t afr[2][2][4];
    uint32_t bfr[2][8][2];

    auto frag_load = [&](uint32_t Ab, uint32_t Bb, int ks, int buf) {
        #pragma unroll
        for (int mt = 0; mt < 2; mt++) {
            uint32_t off = (uint32_t)((a_row + mt * 16) * 128 + ks * 32 + a_kb);
            ldsm_x4(afr[buf][mt][0], afr[buf][mt][1], afr[buf][mt][2],
                    afr[buf][mt][3], Ab + sw128(off));
        }
        #pragma unroll
        for (int nb = 0; nb < 4; nb++) {
            uint32_t off = (uint32_t)((b_row + nb * 16) * 128 + ks * 32 + b_kb);
            uint32_t r0, r1, r2, r3;
            ldsm_x4(r0, r1, r2, r3, Bb + sw128(off));
            bfr[buf][nb * 2 + 0][0] = r0; bfr[buf][nb * 2 + 0][1] = r1;
            bfr[buf][nb * 2 + 1][0] = r2; bfr[buf][nb * 2 + 1][1] = r3;
        }
    };

    // stage 0 ready for everyone, then preload (kt=0, ks=0) fragments
    cp_wait<1>();
    __syncthreads();
    frag_load(sb, sb + A_TILE_BYTES, 0, 0);

    for (int kt = 0; kt < KCHUNKS; kt++) {
        if (kt + 2 < KCHUNKS) { load_stage((kt + 2) % STAGES, kt + 2); cp_commit(); }

        const uint32_t Ab  = sb + (kt % STAGES) * STAGE_BYTES;
        const uint32_t Bb  = Ab + A_TILE_BYTES;
        const uint32_t Abn = sb + ((kt + 1) % STAGES) * STAGE_BYTES;
        const uint32_t Bbn = Abn + A_TILE_BYTES;

        #pragma unroll
        for (int ks = 0; ks < 4; ks++) {
            const int cur = ks & 1;
            if (ks < 3) {
                frag_load(Ab, Bb, ks + 1, cur ^ 1);
            } else if (kt + 1 < KCHUNKS) {
                if (kt == KCHUNKS - 2) cp_wait<0>(); else cp_wait<1>();
                __syncthreads();   // make all threads' stage-(kt+1) copies visible
                frag_load(Abn, Bbn, 0, cur ^ 1);
            }
            #pragma unroll
            for (int mt = 0; mt < 2; mt++)
                #pragma unroll
                for (int nt = 0; nt < 8; nt++)
                    mma_bf16(acc[mt][nt], afr[cur][mt], bfr[cur][nt]);
        }
    }

    // ---------------- epilogue: store fp16 scores + per-row (max,idx,second) -
    #pragma unroll
    for (int mt = 0; mt < 2; mt++) {
        #pragma unroll
        for (int nt = 0; nt < 8; nt++) {
            int row = bm * BM + wm * 32 + mt * 16 + (lane >> 2);
            int col = bn * BN + wn * 64 + nt * 8 + ((lane & 3) << 1);
            *reinterpret_cast<__half2*>(&g_scores[(size_t)row * NCP + col]) =
                __floats2half2_rn(acc[mt][nt][0], acc[mt][nt][1]);
            *reinterpret_cast<__half2*>(&g_scores[(size_t)(row + 8) * NCP + col]) =
                __floats2half2_rn(acc[mt][nt][2], acc[mt][nt][3]);
        }
    }

    __syncthreads();   // stage buffers dead; reuse smem for partial reduction
    float* pm = reinterpret_cast<float*>(smem);        // [2][128]
    float* ps = pm + 256;                              // [2][128]
    int*   pi = reinterpret_cast<int*>(ps + 256);      // [2][128]

    const int cbase = bn * BN + wn * 64 + ((lane & 3) << 1);
    #pragma unroll
    for (int mt = 0; mt < 2; mt++) {
        #pragma unroll
        for (int h = 0; h < 2; h++) {
            float m = -INFINITY, s = -INFINITY;
            int   id = 0;
            #pragma unroll
            for (int nt = 0; nt < 8; nt++) {
                #pragma unroll
                for (int e = 0; e < 2; e++) {
                    int   col = cbase + nt * 8 + e;
                    float v   = acc[mt][nt][h * 2 + e];
                    if (col >= NC) v = -INFINITY;
                    if (v > m) { s = m; m = v; id = col; }
                    else if (v > s) s = v;
                }
            }
            #pragma unroll
            for (int x = 1; x <= 2; x <<= 1) {
                float om = __shfl_xor_sync(0xffffffffu, m, x);
                int   oi = __shfl_xor_sync(0xffffffffu, id, x);
                float os = __shfl_xor_sync(0xffffffffu, s, x);
                comb(m, id, s, om, oi, os);
            }
            if ((lane & 3) == 0) {
                int rl = wm * 32 + mt * 16 + h * 8 + (lane >> 2);
                pm[wn * 128 + rl] = m;
                ps[wn * 128 + rl] = s;
                pi[wn * 128 + rl] = id;
            }
        }
    }
    __syncthreads();

    if (tid < 128) {
        float m = pm[tid];      int id = pi[tid];      float s = ps[tid];
        comb(m, id, s, pm[128 + tid], pi[128 + tid], ps[128 + tid]);
        size_t o = (size_t)(bm * BM + tid) * NBN + bn;
        g_pmax[o] = m; g_psnd[o] = s; g_pidx[o] = id;
    }
}

// ---------------- combine partials -> thr + write unflagged one-hot ---------
__global__ __launch_bounds__(256) void argmax_combine_kernel(float* __restrict__ out) {
    const int s = blockIdx.x * 256 + threadIdx.x;
    if (s >= NS) return;
    const size_t base = (size_t)s * NBN;
    float m = g_pmax[base];  int id = g_pidx[base];  float snd = g_psnd[base];
    #pragma unroll
    for (int p = 1; p < NBN; p++)
        comb(m, id, snd, g_pmax[base + p], g_pidx[base + p], g_psnd[base + p]);

    const float thr = m - MARGIN;
    if (snd >= thr) {
        g_thr[s] = thr;
        int p = atomicAdd(&g_refine_cnt, 1);
        g_refine_list[p] = s;
    } else {
        out[(size_t)s * NC + id] = 1.0f;   // no competitor within margin
    }
}

// ---------------- block-per-sample refine: warp-per-candidate fp64 ----------
// Scan: one batched latency round (4 independent loads/thread).
// Candidates: warp w handles candidates w, w+8, ... in parallel.
// Deterministic: final (value, smaller-class) reduce is order-independent.
__global__ __launch_bounds__(256) void refine_block_kernel(
    const float* __restrict__ x, const float* __restrict__ means,
    float* __restrict__ out) {
    const int tid  = threadIdx.x;
    const int warp = tid >> 5;
    const int lane = tid & 31;

    __shared__ int    cnt;
    __shared__ int    cand[64];
    __shared__ double wv[8];
    __shared__ int    wc[8];

    const int total = g_refine_cnt;
    for (int r = blockIdx.x; r < total; r += gridDim.x) {
        const int    s    = g_refine_list[r];
        const float  thr  = g_thr[s];
        const __half* srow = g_scores + (size_t)s * NCP;
        const float* xr   = x + (size_t)s * ND;

        if (tid == 0) cnt = 0;
        __syncthreads();

        // batched scan: 4 independent loads per thread, then flag
        float v0 = __half2float(srow[tid]);
        float v1 = __half2float(srow[tid + 256]);
        float v2 = __half2float(srow[tid + 512]);
        float v3 = (tid + 768 < NC) ? __half2float(srow[tid + 768]) : -1e30f;
        if (v0 >= thr) { int p = atomicAdd(&cnt, 1); if (p < 64) cand[p] = tid; }
        if (v1 >= thr) { int p = atomicAdd(&cnt, 1); if (p < 64) cand[p] = tid + 256; }
        if (v2 >= thr) { int p = atomicAdd(&cnt, 1); if (p < 64) cand[p] = tid + 512; }
        if (v3 >= thr) { int p = atomicAdd(&cnt, 1); if (p < 64) cand[p] = tid + 768; }
        __syncthreads();

        const int nc = (cnt < 64) ? cnt : 64;

        double bestv = -1e300;
        int    bestc = 1 << 30;
        for (int ci = warp; ci < nc; ci += 8) {
            const int cls = cand[ci];
            const float* mr = means + (size_t)cls * ND;
            double a0 = 0, a1 = 0, a2 = 0, a3 = 0, a4 = 0, a5 = 0, a6 = 0, a7 = 0;
            #pragma unroll
            for (int t = 0; t < 64; t += 8) {
                int e = lane + 32 * t;
                a0 += (double)xr[e]         * (double)mr[e];
                a1 += (double)xr[e + 32]    * (double)mr[e + 32];
                a2 += (double)xr[e + 64]    * (double)mr[e + 64];
                a3 += (double)xr[e + 96]    * (double)mr[e + 96];
                a4 += (double)xr[e + 128]   * (double)mr[e + 128];
                a5 += (double)xr[e + 160]   * (double)mr[e + 160];
                a6 += (double)xr[e + 192]   * (double)mr[e + 192];
                a7 += (double)xr[e + 224]   * (double)mr[e + 224];
            }
            double tot = ((a0 + a1) + (a2 + a3)) + ((a4 + a5) + (a6 + a7));
            #pragma unroll
            for (int o = 16; o > 0; o >>= 1)
                tot += __shfl_down_sync(0xffffffffu, tot, o);
            tot = __shfl_sync(0xffffffffu, tot, 0);
            if (tot > bestv || (tot == bestv && cls < bestc)) {
                bestv = tot; bestc = cls;
            }
        }
        if (lane == 0) { wv[warp] = bestv; wc[warp] = bestc; }
        __syncthreads();

        if (tid == 0) {
            double bv = wv[0]; int bc = wc[0];
            #pragma unroll
            for (int w = 1; w < 8; w++)
                if (wv[w] > bv || (wv[w] == bv && wc[w] < bc)) { bv = wv[w]; bc = wc[w]; }
            out[(size_t)s * NC + bc] = 1.0f;
        }
        __syncthreads();
    }
}

// ---------------- launch ----------------------------------------------------
extern "C" void kernel_launch(void* const* d_in, const int* in_sizes, int n_in,
                              void* d_out, int out_size) {
    const float* x     = (const float*)d_in[0];
    const float* means = (const float*)d_in[1];
    float* out = (float*)d_out;

    cudaFuncSetAttribute(gemm_mma8_kernel,
                         cudaFuncAttributeMaxDynamicSharedMemorySize, SMEM_TOTAL);

    const int cvt_blocks = (int)((XCHUNKS + MCHUNKS) / 256);
    cvt_all_kernel<<<cvt_blocks, 256>>>(                          // launch 1
        reinterpret_cast<const float4*>(x),
        reinterpret_cast<const float4*>(means));
    gemm_mma8_kernel<<<dim3(NCP / BN, NS / BM), 256, SMEM_TOTAL>>>( // launch 2
        reinterpret_cast<float4*>(out));
    argmax_combine_kernel<<<NS / 256, 256>>>(out);                // launch 3
    refine_block_kernel<<<4096, 256>>>(x, means, out);            // launch 4 (ncu)
}

// round 15
// speedup vs baseline: 1.0844x; 1.0267x over previous
#include <cuda_runtime.h>
#include <cuda_bf16.h>
#include <cuda_fp16.h>
#include <stdint.h>
#include <math.h>

#define NS 16384
#define ND 2048
#define NC 1000
#define NCP 1024

#define MARGIN 1.5f

// GEMM tiling: 128x128 block, 8 warps (4x2), warp tile 32x64, 2 CTAs/SM
#define BM 128
#define BN 128
#define BK 64                  // K per chunk: 128 bytes/row (SW128 atom)
#define KCHUNKS (ND / BK)      // 32
#define STAGES 3
#define A_TILE_BYTES (BM * BK * 2)   // 16384
#define B_TILE_BYTES (BN * BK * 2)   // 16384
#define STAGE_BYTES (A_TILE_BYTES + B_TILE_BYTES)  // 32768
#define SMEM_TOTAL (STAGES * STAGE_BYTES + 1024)

#define NBN (NCP / BN)         // 8 partials per row

// out-zeroing slice per GEMM CTA: NS*NC/1024 = 16000 floats = 4000 float4
#define ZERO_F4_PER_CTA 4000

// ---------------- scratch (static device globals) ---------------------------
__device__ __nv_bfloat16 g_xb[(size_t)NS * ND];    // tiled: [bm][kt][128x64 SW128]
__device__ __nv_bfloat16 g_mb[(size_t)NCP * ND];   // tiled: [bn][kt][128x64 SW128]
__device__ __half        g_scores[(size_t)NS * NCP];
__device__ float         g_pmax[(size_t)NS * NBN];
__device__ float         g_psnd[(size_t)NS * NBN];
__device__ int           g_pidx[(size_t)NS * NBN];
__device__ float         g_thr[NS];
__device__ int           g_refine_list[NS];
__device__ int           g_refine_cnt;

// ---------------- helpers ----------------------------------------------------
__device__ __forceinline__ uint32_t smem_u32(const void* p) {
    return (uint32_t)__cvta_generic_to_shared(p);
}
__host__ __device__ __forceinline__ uint32_t sw128(uint32_t off) {
    return off ^ ((off >> 3) & 0x70);
}
__device__ __forceinline__ void cp16(uint32_t dst, const void* src) {
    asm volatile("cp.async.cg.shared.global [%0], [%1], 16;"
                 :: "r"(dst), "l"(src) : "memory");
}
__device__ __forceinline__ void cp_commit() {
    asm volatile("cp.async.commit_group;" ::: "memory");
}
template <int N>
__device__ __forceinline__ void cp_wait() {
    asm volatile("cp.async.wait_group %0;" :: "n"(N) : "memory");
}
__device__ __forceinline__ void ldsm_x4(uint32_t& r0, uint32_t& r1, uint32_t& r2,
                                        uint32_t& r3, uint32_t addr) {
    asm volatile("ldmatrix.sync.aligned.m8n8.x4.shared.b16 {%0,%1,%2,%3}, [%4];\n"
                 : "=r"(r0), "=r"(r1), "=r"(r2), "=r"(r3) : "r"(addr));
}
__device__ __forceinline__ void mma_bf16(float* c, const uint32_t* a, const uint32_t* b) {
    asm volatile(
        "mma.sync.aligned.m16n8k16.row.col.f32.bf16.bf16.f32 "
        "{%0,%1,%2,%3}, {%4,%5,%6,%7}, {%8,%9}, {%0,%1,%2,%3};\n"
        : "+f"(c[0]), "+f"(c[1]), "+f"(c[2]), "+f"(c[3])
        : "r"(a[0]), "r"(a[1]), "r"(a[2]), "r"(a[3]), "r"(b[0]), "r"(b[1]));
}
// combine (max, idx, second) partials; prefer larger val, then smaller idx
__device__ __forceinline__ void comb(float& m, int& id, float& s,
                                     float om, int oid, float os) {
    if (om > m || (om == m && oid < id)) {
        s = fmaxf(m, os); m = om; id = oid;
    } else {
        s = fmaxf(s, om);
    }
}

// ---------------- merged convert kernel (x then means) ----------------------
#define XCHUNKS (NS * (size_t)ND / 8)     // 4,194,304
#define MCHUNKS ((size_t)NCP * ND / 8)    // 524,288

__global__ __launch_bounds__(256) void cvt_all_kernel(const float4* __restrict__ x,
                                                      const float4* __restrict__ m) {
    size_t g = (size_t)blockIdx.x * 256 + threadIdx.x;
    if (g < XCHUNKS) {
        uint32_t gg = (uint32_t)g;
        uint32_t tile = gg >> 10;                  // [bm(128)][kt(32)]
        uint32_t w    = gg & 1023;
        uint32_t tm = tile >> 5, tk = tile & 31;
        uint32_t r  = w >> 3, cgrp = w & 7;
        uint32_t row = tm * 128 + r;
        size_t src = (size_t)row * 512 + tk * 16 + cgrp * 2;
        float4 v0 = x[src];
        float4 v1 = x[src + 1];
        __nv_bfloat162 b0 = __floats2bfloat162_rn(v0.x, v0.y);
        __nv_bfloat162 b1 = __floats2bfloat162_rn(v0.z, v0.w);
        __nv_bfloat162 b2 = __floats2bfloat162_rn(v1.x, v1.y);
        __nv_bfloat162 b3 = __floats2bfloat162_rn(v1.z, v1.w);
        uint4 q;
        q.x = *reinterpret_cast<uint32_t*>(&b0);
        q.y = *reinterpret_cast<uint32_t*>(&b1);
        q.z = *reinterpret_cast<uint32_t*>(&b2);
        q.w = *reinterpret_cast<uint32_t*>(&b3);
        *reinterpret_cast<uint4*>((char*)g_xb + (size_t)tile * A_TILE_BYTES +
                                  sw128(w * 16)) = q;
        if (gg == 0) g_refine_cnt = 0;
    } else {
        uint32_t gg = (uint32_t)(g - XCHUNKS);
        uint32_t tile = gg >> 10;                  // [bn(8)][kt(32)]
        uint32_t w    = gg & 1023;
        uint32_t tb = tile >> 5, tk = tile & 31;
        uint32_t r  = w >> 3, cgrp = w & 7;
        uint32_t row = tb * 128 + r;
        float4 v0 = make_float4(0.f, 0.f, 0.f, 0.f), v1 = v0;
        if (row < NC) {
            size_t src = (size_t)row * 512 + tk * 16 + cgrp * 2;
            v0 = m[src];
            v1 = m[src + 1];
        }
        __nv_bfloat162 b0 = __floats2bfloat162_rn(v0.x, v0.y);
        __nv_bfloat162 b1 = __floats2bfloat162_rn(v0.z, v0.w);
        __nv_bfloat162 b2 = __floats2bfloat162_rn(v1.x, v1.y);
        __nv_bfloat162 b3 = __floats2bfloat162_rn(v1.z, v1.w);
        uint4 q;
        q.x = *reinterpret_cast<uint32_t*>(&b0);
        q.y = *reinterpret_cast<uint32_t*>(&b1);
        q.z = *reinterpret_cast<uint32_t*>(&b2);
        q.w = *reinterpret_cast<uint32_t*>(&b3);
        *reinterpret_cast<uint4*>((char*)g_mb + (size_t)tile * B_TILE_BYTES +
                                  sw128(w * 16)) = q;
    }
}

// ---------------- GEMM: 128x128 block, 8 warps 4x2, warp 32x64 --------------
// Cross-chunk fragment prefetch + fused output zeroing in the prologue.
__global__ __launch_bounds__(256, 2) void gemm_mma8_kernel(float4* __restrict__ out) {
    extern __shared__ char smem[];
    const uint32_t sb = (smem_u32(smem) + 1023u) & ~1023u;

    const int tid  = threadIdx.x;
    const int lane = tid & 31;
    const int wid  = tid >> 5;
    const int wm   = wid >> 1;   // 0..3 -> 32-row slab
    const int wn   = wid & 1;    // 0..1 -> 64-col slab
    const int bn   = blockIdx.x; // 0..7
    const int bm   = blockIdx.y; // 0..127

    const char* gA = (const char*)g_xb + (size_t)bm * KCHUNKS * A_TILE_BYTES;
    const char* gB = (const char*)g_mb + (size_t)bn * KCHUNKS * B_TILE_BYTES;

    auto load_stage = [&](int s, int kt) {
        uint32_t Ad = sb + s * STAGE_BYTES;
        const char* Asrc = gA + (size_t)kt * A_TILE_BYTES;
        #pragma unroll
        for (int i = 0; i < 4; i++) {
            int ch = tid + i * 256;
            cp16(Ad + ch * 16, Asrc + ch * 16);
        }
        uint32_t Bd = Ad + A_TILE_BYTES;
        const char* Bsrc = gB + (size_t)kt * B_TILE_BYTES;
        #pragma unroll
        for (int i = 0; i < 4; i++) {
            int ch = tid + i * 256;
            cp16(Bd + ch * 16, Bsrc + ch * 16);
        }
    };

    float acc[2][8][4];
    #pragma unroll
    for (int i = 0; i < 2; i++)
        #pragma unroll
        for (int j = 0; j < 8; j++)
            #pragma unroll
            for (int k = 0; k < 4; k++) acc[i][j][k] = 0.f;

    load_stage(0, 0); cp_commit();
    load_stage(1, 1); cp_commit();

    // fused zero of this CTA's out slice (overlaps the cp.async prefetch)
    {
        const int cta = bm * NBN + bn;               // 0..1023
        float4* z = out + (size_t)cta * ZERO_F4_PER_CTA;
        const float4 zf = make_float4(0.f, 0.f, 0.f, 0.f);
        #pragma unroll
        for (int i = 0; i < 16; i++) {
            int ch = tid + i * 256;
            if (ch < ZERO_F4_PER_CTA) z[ch] = zf;
        }
    }

    const int a_row = wm * 32 + (lane & 15);
    const int a_kb  = ((lane >> 4) << 3) * 2;
    const int b_row = wn * 64 + ((lane >> 4) << 3) + (lane & 7);
    const int b_kb  = (((lane >> 3) & 1) << 3) * 2;

    uint32_t afr[2][2][4];
    uint32_t bfr[2][8][2];

    auto frag_load = [&](uint32_t Ab, uint32_t Bb, int ks, int buf) {
        #pragma unroll
        for (int mt = 0; mt < 2; mt++) {
            uint32_t off = (uint32_t)((a_row + mt * 16) * 128 + ks * 32 + a_kb);
            ldsm_x4(afr[buf][mt][0], afr[buf][mt][1], afr[buf][mt][2],
                    afr[buf][mt][3], Ab + sw128(off));
        }
        #pragma unroll
        for (int nb = 0; nb < 4; nb++) {
            uint32_t off = (uint32_t)((b_row + nb * 16) * 128 + ks * 32 + b_kb);
            uint32_t r0, r1, r2, r3;
            ldsm_x4(r0, r1, r2, r3, Bb + sw128(off));
            bfr[buf][nb * 2 + 0][0] = r0; bfr[buf][nb * 2 + 0][1] = r1;
            bfr[buf][nb * 2 + 1][0] = r2; bfr[buf][nb * 2 + 1][1] = r3;
        }
    };

    // stage 0 ready for everyone, then preload (kt=0, ks=0) fragments
    cp_wait<1>();
    __syncthreads();
    frag_load(sb, sb + A_TILE_BYTES, 0, 0);

    for (int kt = 0; kt < KCHUNKS; kt++) {
        if (kt + 2 < KCHUNKS) { load_stage((kt + 2) % STAGES, kt + 2); cp_commit(); }

        const uint32_t Ab  = sb + (kt % STAGES) * STAGE_BYTES;
        const uint32_t Bb  = Ab + A_TILE_BYTES;
        const uint32_t Abn = sb + ((kt + 1) % STAGES) * STAGE_BYTES;
        const uint32_t Bbn = Abn + A_TILE_BYTES;

        #pragma unroll
        for (int ks = 0; ks < 4; ks++) {
            const int cur = ks & 1;
            if (ks < 3) {
                frag_load(Ab, Bb, ks + 1, cur ^ 1);
            } else if (kt + 1 < KCHUNKS) {
                if (kt == KCHUNKS - 2) cp_wait<0>(); else cp_wait<1>();
                __syncthreads();   // make all threads' stage-(kt+1) copies visible
                frag_load(Abn, Bbn, 0, cur ^ 1);
            }
            #pragma unroll
            for (int mt = 0; mt < 2; mt++)
                #pragma unroll
                for (int nt = 0; nt < 8; nt++)
                    mma_bf16(acc[mt][nt], afr[cur][mt], bfr[cur][nt]);
        }
    }

    // ---------------- epilogue: store fp16 scores + per-row (max,idx,second) -
    #pragma unroll
    for (int mt = 0; mt < 2; mt++) {
        #pragma unroll
        for (int nt = 0; nt < 8; nt++) {
            int row = bm * BM + wm * 32 + mt * 16 + (lane >> 2);
            int col = bn * BN + wn * 64 + nt * 8 + ((lane & 3) << 1);
            *reinterpret_cast<__half2*>(&g_scores[(size_t)row * NCP + col]) =
                __floats2half2_rn(acc[mt][nt][0], acc[mt][nt][1]);
            *reinterpret_cast<__half2*>(&g_scores[(size_t)(row + 8) * NCP + col]) =
                __floats2half2_rn(acc[mt][nt][2], acc[mt][nt][3]);
        }
    }

    __syncthreads();   // stage buffers dead; reuse smem for partial reduction
    float* pm = reinterpret_cast<float*>(smem);        // [2][128]
    float* ps = pm + 256;                              // [2][128]
    int*   pi = reinterpret_cast<int*>(ps + 256);      // [2][128]

    const int cbase = bn * BN + wn * 64 + ((lane & 3) << 1);
    #pragma unroll
    for (int mt = 0; mt < 2; mt++) {
        #pragma unroll
        for (int h = 0; h < 2; h++) {
            float m = -INFINITY, s = -INFINITY;
            int   id = 0;
            #pragma unroll
            for (int nt = 0; nt < 8; nt++) {
                #pragma unroll
                for (int e = 0; e < 2; e++) {
                    int   col = cbase + nt * 8 + e;
                    float v   = acc[mt][nt][h * 2 + e];
                    if (col >= NC) v = -INFINITY;
                    if (v > m) { s = m; m = v; id = col; }
                    else if (v > s) s = v;
                }
            }
            #pragma unroll
            for (int x = 1; x <= 2; x <<= 1) {
                float om = __shfl_xor_sync(0xffffffffu, m, x);
                int   oi = __shfl_xor_sync(0xffffffffu, id, x);
                float os = __shfl_xor_sync(0xffffffffu, s, x);
                comb(m, id, s, om, oi, os);
            }
            if ((lane & 3) == 0) {
                int rl = wm * 32 + mt * 16 + h * 8 + (lane >> 2);
                pm[wn * 128 + rl] = m;
                ps[wn * 128 + rl] = s;
                pi[wn * 128 + rl] = id;
            }
        }
    }
    __syncthreads();

    if (tid < 128) {
        float m = pm[tid];      int id = pi[tid];      float s = ps[tid];
        comb(m, id, s, pm[128 + tid], pi[128 + tid], ps[128 + tid]);
        size_t o = (size_t)(bm * BM + tid) * NBN + bn;
        g_pmax[o] = m; g_psnd[o] = s; g_pidx[o] = id;
    }
}

// ---------------- combine partials -> thr + write unflagged one-hot ---------
__global__ __launch_bounds__(256) void argmax_combine_kernel(float* __restrict__ out) {
    const int s = blockIdx.x * 256 + threadIdx.x;
    if (s >= NS) return;
    const size_t base = (size_t)s * NBN;
    float m = g_pmax[base];  int id = g_pidx[base];  float snd = g_psnd[base];
    #pragma unroll
    for (int p = 1; p < NBN; p++)
        comb(m, id, snd, g_pmax[base + p], g_pidx[base + p], g_psnd[base + p]);

    const float thr = m - MARGIN;
    if (snd >= thr) {
        g_thr[s] = thr;
        int p = atomicAdd(&g_refine_cnt, 1);
        g_refine_list[p] = s;
    } else {
        out[(size_t)s * NC + id] = 1.0f;   // no competitor within margin
    }
}

// ---------------- refine: 64-thr block/sample, 8 CTAs/SM, warp/candidate ----
// Scan via __half2 (8 independent loads/thread = one latency round).
// Candidates split across the block's 2 warps. Deterministic final reduce.
__global__ __launch_bounds__(64, 8) void refine_small_kernel(
    const float* __restrict__ x, const float* __restrict__ means,
    float* __restrict__ out) {
    const int tid  = threadIdx.x;
    const int warp = tid >> 5;
    const int lane = tid & 31;

    __shared__ int    cnt;
    __shared__ int    cand[64];
    __shared__ double wv[2];
    __shared__ int    wc[2];

    const int total = g_refine_cnt;
    for (int r = blockIdx.x; r < total; r += gridDim.x) {
        const int    s    = g_refine_list[r];
        const float  thr  = g_thr[s];
        const __half2* srow2 =
            reinterpret_cast<const __half2*>(g_scores + (size_t)s * NCP);
        const float* xr = x + (size_t)s * ND;

        if (tid == 0) cnt = 0;
        __syncthreads();

        // batched scan: 8 independent half2 loads per thread (512 half2 total)
        float2 vv[8];
        #pragma unroll
        for (int i = 0; i < 8; i++)
            vv[i] = __half22float2(srow2[tid + i * 64]);
        #pragma unroll
        for (int i = 0; i < 8; i++) {
            int j = (tid + i * 64) * 2;
            if (j < NC && vv[i].x >= thr) {
                int p = atomicAdd(&cnt, 1); if (p < 64) cand[p] = j;
            }
            if (j + 1 < NC && vv[i].y >= thr) {
                int p = atomicAdd(&cnt, 1); if (p < 64) cand[p] = j + 1;
            }
        }
        __syncthreads();

        const int nc = (cnt < 64) ? cnt : 64;

        double bestv = -1e300;
        int    bestc = 1 << 30;
        for (int ci = warp; ci < nc; ci += 2) {
            const int cls = cand[ci];
            const float* mr = means + (size_t)cls * ND;
            double a0 = 0, a1 = 0, a2 = 0, a3 = 0, a4 = 0, a5 = 0, a6 = 0, a7 = 0;
            #pragma unroll
            for (int t = 0; t < 64; t += 8) {
                int e = lane + 32 * t;
                a0 += (double)xr[e]         * (double)mr[e];
                a1 += (double)xr[e + 32]    * (double)mr[e + 32];
                a2 += (double)xr[e + 64]    * (double)mr[e + 64];
                a3 += (double)xr[e + 96]    * (double)mr[e + 96];
                a4 += (double)xr[e + 128]   * (double)mr[e + 128];
                a5 += (double)xr[e + 160]   * (double)mr[e + 160];
                a6 += (double)xr[e + 192]   * (double)mr[e + 192];
                a7 += (double)xr[e + 224]   * (double)mr[e + 224];
            }
            double tot = ((a0 + a1) + (a2 + a3)) + ((a4 + a5) + (a6 + a7));
            #pragma unroll
            for (int o = 16; o > 0; o >>= 1)
                tot += __shfl_down_sync(0xffffffffu, tot, o);
            tot = __shfl_sync(0xffffffffu, tot, 0);
            if (tot > bestv || (tot == bestv && cls < bestc)) {
                bestv = tot; bestc = cls;
            }
        }
        if (lane == 0) { wv[warp] = bestv; wc[warp] = bestc; }
        __syncthreads();

        if (tid == 0) {
            double bv = wv[0]; int bc = wc[0];
            if (wv[1] > bv || (wv[1] == bv && wc[1] < bc)) { bv = wv[1]; bc = wc[1]; }
            out[(size_t)s * NC + bc] = 1.0f;
        }
        __syncthreads();
    }
}

// ---------------- launch ----------------------------------------------------
extern "C" void kernel_launch(void* const* d_in, const int* in_sizes, int n_in,
                              void* d_out, int out_size) {
    const float* x     = (const float*)d_in[0];
    const float* means = (const float*)d_in[1];
    float* out = (float*)d_out;

    cudaFuncSetAttribute(gemm_mma8_kernel,
                         cudaFuncAttributeMaxDynamicSharedMemorySize, SMEM_TOTAL);

    const int cvt_blocks = (int)((XCHUNKS + MCHUNKS) / 256);
    cvt_all_kernel<<<cvt_blocks, 256>>>(                          // launch 1
        reinterpret_cast<const float4*>(x),
        reinterpret_cast<const float4*>(means));
    gemm_mma8_kernel<<<dim3(NCP / BN, NS / BM), 256, SMEM_TOTAL>>>( // launch 2
        reinterpret_cast<float4*>(out));
    argmax_combine_kernel<<<NS / 256, 256>>>(out);                // launch 3
    refine_small_kernel<<<4096, 64>>>(x, means, out);             // launch 4 (ncu)
}

// round 16
// speedup vs baseline: 1.2006x; 1.1071x over previous
#include <cuda_runtime.h>
#include <cuda_bf16.h>
#include <cuda_fp16.h>
#include <stdint.h>
#include <math.h>

#define NS 16384
#define ND 2048
#define NC 1000
#define NCP 1024

#define MARGIN 0.8f   // 7 sigma of score-diff error (bf16 gemm + fp16 storage)

// GEMM tiling: 128x128 block, 8 warps (4x2), warp tile 32x64, 2 CTAs/SM
#define BM 128
#define BN 128
#define BK 64                  // K per chunk: 128 bytes/row (SW128 atom)
#define KCHUNKS (ND / BK)      // 32
#define STAGES 3
#define A_TILE_BYTES (BM * BK * 2)   // 16384
#define B_TILE_BYTES (BN * BK * 2)   // 16384
#define STAGE_BYTES (A_TILE_BYTES + B_TILE_BYTES)  // 32768
#define SMEM_TOTAL (STAGES * STAGE_BYTES + 1024)

#define NBN (NCP / BN)         // 8 partials per row

// out-zeroing slice per GEMM CTA: NS*NC/1024 = 16000 floats = 4000 float4
#define ZERO_F4_PER_CTA 4000

// ---------------- scratch (static device globals) ---------------------------
__device__ __nv_bfloat16 g_xb[(size_t)NS * ND];    // tiled: [bm][kt][128x64 SW128]
__device__ __nv_bfloat16 g_mb[(size_t)NCP * ND];   // tiled: [bn][kt][128x64 SW128]
__device__ __half        g_scores[(size_t)NS * NCP];
__device__ float         g_pmax[(size_t)NS * NBN];
__device__ float         g_psnd[(size_t)NS * NBN];
__device__ int           g_pidx[(size_t)NS * NBN];
__device__ float         g_thr[NS];
__device__ int           g_refine_list[NS];
__device__ int           g_refine_cnt;

// ---------------- helpers ----------------------------------------------------
__device__ __forceinline__ uint32_t smem_u32(const void* p) {
    return (uint32_t)__cvta_generic_to_shared(p);
}
__host__ __device__ __forceinline__ uint32_t sw128(uint32_t off) {
    return off ^ ((off >> 3) & 0x70);
}
__device__ __forceinline__ void cp16(uint32_t dst, const void* src) {
    asm volatile("cp.async.cg.shared.global [%0], [%1], 16;"
                 :: "r"(dst), "l"(src) : "memory");
}
__device__ __forceinline__ void cp_commit() {
    asm volatile("cp.async.commit_group;" ::: "memory");
}
template <int N>
__device__ __forceinline__ void cp_wait() {
    asm volatile("cp.async.wait_group %0;" :: "n"(N) : "memory");
}
__device__ __forceinline__ void ldsm_x4(uint32_t& r0, uint32_t& r1, uint32_t& r2,
                                        uint32_t& r3, uint32_t addr) {
    asm volatile("ldmatrix.sync.aligned.m8n8.x4.shared.b16 {%0,%1,%2,%3}, [%4];\n"
                 : "=r"(r0), "=r"(r1), "=r"(r2), "=r"(r3) : "r"(addr));
}
__device__ __forceinline__ void mma_bf16(float* c, const uint32_t* a, const uint32_t* b) {
    asm volatile(
        "mma.sync.aligned.m16n8k16.row.col.f32.bf16.bf16.f32 "
        "{%0,%1,%2,%3}, {%4,%5,%6,%7}, {%8,%9}, {%0,%1,%2,%3};\n"
        : "+f"(c[0]), "+f"(c[1]), "+f"(c[2]), "+f"(c[3])
        : "r"(a[0]), "r"(a[1]), "r"(a[2]), "r"(a[3]), "r"(b[0]), "r"(b[1]));
}
// combine (max, idx, second) partials; prefer larger val, then smaller idx
__device__ __forceinline__ void comb(float& m, int& id, float& s,
                                     float om, int oid, float os) {
    if (om > m || (om == m && oid < id)) {
        s = fmaxf(m, os); m = om; id = oid;
    } else {
        s = fmaxf(s, om);
    }
}

// ---------------- merged convert kernel (x then means) ----------------------
#define XCHUNKS (NS * (size_t)ND / 8)     // 4,194,304
#define MCHUNKS ((size_t)NCP * ND / 8)    // 524,288

__global__ __launch_bounds__(256) void cvt_all_kernel(const float4* __restrict__ x,
                                                      const float4* __restrict__ m) {
    size_t g = (size_t)blockIdx.x * 256 + threadIdx.x;
    if (g < XCHUNKS) {
        uint32_t gg = (uint32_t)g;
        uint32_t tile = gg >> 10;                  // [bm(128)][kt(32)]
        uint32_t w    = gg & 1023;
        uint32_t tm = tile >> 5, tk = tile & 31;
        uint32_t r  = w >> 3, cgrp = w & 7;
        uint32_t row = tm * 128 + r;
        size_t src = (size_t)row * 512 + tk * 16 + cgrp * 2;
        float4 v0 = x[src];
        float4 v1 = x[src + 1];
        __nv_bfloat162 b0 = __floats2bfloat162_rn(v0.x, v0.y);
        __nv_bfloat162 b1 = __floats2bfloat162_rn(v0.z, v0.w);
        __nv_bfloat162 b2 = __floats2bfloat162_rn(v1.x, v1.y);
        __nv_bfloat162 b3 = __floats2bfloat162_rn(v1.z, v1.w);
        uint4 q;
        q.x = *reinterpret_cast<uint32_t*>(&b0);
        q.y = *reinterpret_cast<uint32_t*>(&b1);
        q.z = *reinterpret_cast<uint32_t*>(&b2);
        q.w = *reinterpret_cast<uint32_t*>(&b3);
        *reinterpret_cast<uint4*>((char*)g_xb + (size_t)tile * A_TILE_BYTES +
                                  sw128(w * 16)) = q;
        if (gg == 0) g_refine_cnt = 0;
    } else {
        uint32_t gg = (uint32_t)(g - XCHUNKS);
        uint32_t tile = gg >> 10;                  // [bn(8)][kt(32)]
        uint32_t w    = gg & 1023;
        uint32_t tb = tile >> 5, tk = tile & 31;
        uint32_t r  = w >> 3, cgrp = w & 7;
        uint32_t row = tb * 128 + r;
        float4 v0 = make_float4(0.f, 0.f, 0.f, 0.f), v1 = v0;
        if (row < NC) {
            size_t src = (size_t)row * 512 + tk * 16 + cgrp * 2;
            v0 = m[src];
            v1 = m[src + 1];
        }
        __nv_bfloat162 b0 = __floats2bfloat162_rn(v0.x, v0.y);
        __nv_bfloat162 b1 = __floats2bfloat162_rn(v0.z, v0.w);
        __nv_bfloat162 b2 = __floats2bfloat162_rn(v1.x, v1.y);
        __nv_bfloat162 b3 = __floats2bfloat162_rn(v1.z, v1.w);
        uint4 q;
        q.x = *reinterpret_cast<uint32_t*>(&b0);
        q.y = *reinterpret_cast<uint32_t*>(&b1);
        q.z = *reinterpret_cast<uint32_t*>(&b2);
        q.w = *reinterpret_cast<uint32_t*>(&b3);
        *reinterpret_cast<uint4*>((char*)g_mb + (size_t)tile * B_TILE_BYTES +
                                  sw128(w * 16)) = q;
    }
}

// ---------------- GEMM: 128x128 block, 8 warps 4x2, warp 32x64 --------------
// Cross-chunk fragment prefetch + fused output zeroing in the prologue.
__global__ __launch_bounds__(256, 2) void gemm_mma8_kernel(float4* __restrict__ out) {
    extern __shared__ char smem[];
    const uint32_t sb = (smem_u32(smem) + 1023u) & ~1023u;

    const int tid  = threadIdx.x;
    const int lane = tid & 31;
    const int wid  = tid >> 5;
    const int wm   = wid >> 1;   // 0..3 -> 32-row slab
    const int wn   = wid & 1;    // 0..1 -> 64-col slab
    const int bn   = blockIdx.x; // 0..7
    const int bm   = blockIdx.y; // 0..127

    const char* gA = (const char*)g_xb + (size_t)bm * KCHUNKS * A_TILE_BYTES;
    const char* gB = (const char*)g_mb + (size_t)bn * KCHUNKS * B_TILE_BYTES;

    auto load_stage = [&](int s, int kt) {
        uint32_t Ad = sb + s * STAGE_BYTES;
        const char* Asrc = gA + (size_t)kt * A_TILE_BYTES;
        #pragma unroll
        for (int i = 0; i < 4; i++) {
            int ch = tid + i * 256;
            cp16(Ad + ch * 16, Asrc + ch * 16);
        }
        uint32_t Bd = Ad + A_TILE_BYTES;
        const char* Bsrc = gB + (size_t)kt * B_TILE_BYTES;
        #pragma unroll
        for (int i = 0; i < 4; i++) {
            int ch = tid + i * 256;
            cp16(Bd + ch * 16, Bsrc + ch * 16);
        }
    };

    float acc[2][8][4];
    #pragma unroll
    for (int i = 0; i < 2; i++)
        #pragma unroll
        for (int j = 0; j < 8; j++)
            #pragma unroll
            for (int k = 0; k < 4; k++) acc[i][j][k] = 0.f;

    load_stage(0, 0); cp_commit();
    load_stage(1, 1); cp_commit();

    // fused zero of this CTA's out slice (overlaps the cp.async prefetch)
    {
        const int cta = bm * NBN + bn;               // 0..1023
        float4* z = out + (size_t)cta * ZERO_F4_PER_CTA;
        const float4 zf = make_float4(0.f, 0.f, 0.f, 0.f);
        #pragma unroll
        for (int i = 0; i < 16; i++) {
            int ch = tid + i * 256;
            if (ch < ZERO_F4_PER_CTA) z[ch] = zf;
        }
    }

    const int a_row = wm * 32 + (lane & 15);
    const int a_kb  = ((lane >> 4) << 3) * 2;
    const int b_row = wn * 64 + ((lane >> 4) << 3) + (lane & 7);
    const int b_kb  = (((lane >> 3) & 1) << 3) * 2;

    uint32_t afr[2][2][4];
    uint32_t bfr[2][8][2];

    auto frag_load = [&](uint32_t Ab, uint32_t Bb, int ks, int buf) {
        #pragma unroll
        for (int mt = 0; mt < 2; mt++) {
            uint32_t off = (uint32_t)((a_row + mt * 16) * 128 + ks * 32 + a_kb);
            ldsm_x4(afr[buf][mt][0], afr[buf][mt][1], afr[buf][mt][2],
                    afr[buf][mt][3], Ab + sw128(off));
        }
        #pragma unroll
        for (int nb = 0; nb < 4; nb++) {
            uint32_t off = (uint32_t)((b_row + nb * 16) * 128 + ks * 32 + b_kb);
            uint32_t r0, r1, r2, r3;
            ldsm_x4(r0, r1, r2, r3, Bb + sw128(off));
            bfr[buf][nb * 2 + 0][0] = r0; bfr[buf][nb * 2 + 0][1] = r1;
            bfr[buf][nb * 2 + 1][0] = r2; bfr[buf][nb * 2 + 1][1] = r3;
        }
    };

    // stage 0 ready for everyone, then preload (kt=0, ks=0) fragments
    cp_wait<1>();
    __syncthreads();
    frag_load(sb, sb + A_TILE_BYTES, 0, 0);

    for (int kt = 0; kt < KCHUNKS; kt++) {
        if (kt + 2 < KCHUNKS) { load_stage((kt + 2) % STAGES, kt + 2); cp_commit(); }

        const uint32_t Ab  = sb + (kt % STAGES) * STAGE_BYTES;
        const uint32_t Bb  = Ab + A_TILE_BYTES;
        const uint32_t Abn = sb + ((kt + 1) % STAGES) * STAGE_BYTES;
        const uint32_t Bbn = Abn + A_TILE_BYTES;

        #pragma unroll
        for (int ks = 0; ks < 4; ks++) {
            const int cur = ks & 1;
            if (ks < 3) {
                frag_load(Ab, Bb, ks + 1, cur ^ 1);
            } else if (kt + 1 < KCHUNKS) {
                if (kt == KCHUNKS - 2) cp_wait<0>(); else cp_wait<1>();
                __syncthreads();   // make all threads' stage-(kt+1) copies visible
                frag_load(Abn, Bbn, 0, cur ^ 1);
            }
            #pragma unroll
            for (int mt = 0; mt < 2; mt++)
                #pragma unroll
                for (int nt = 0; nt < 8; nt++)
                    mma_bf16(acc[mt][nt], afr[cur][mt], bfr[cur][nt]);
        }
    }

    // ---------------- epilogue: store fp16 scores + per-row (max,idx,second) -
    #pragma unroll
    for (int mt = 0; mt < 2; mt++) {
        #pragma unroll
        for (int nt = 0; nt < 8; nt++) {
            int row = bm * BM + wm * 32 + mt * 16 + (lane >> 2);
            int col = bn * BN + wn * 64 + nt * 8 + ((lane & 3) << 1);
            *reinterpret_cast<__half2*>(&g_scores[(size_t)row * NCP + col]) =
                __floats2half2_rn(acc[mt][nt][0], acc[mt][nt][1]);
            *reinterpret_cast<__half2*>(&g_scores[(size_t)(row + 8) * NCP + col]) =
                __floats2half2_rn(acc[mt][nt][2], acc[mt][nt][3]);
        }
    }

    __syncthreads();   // stage buffers dead; reuse smem for partial reduction
    float* pm = reinterpret_cast<float*>(smem);        // [2][128]
    float* ps = pm + 256;                              // [2][128]
    int*   pi = reinterpret_cast<int*>(ps + 256);      // [2][128]

    const int cbase = bn * BN + wn * 64 + ((lane & 3) << 1);
    #pragma unroll
    for (int mt = 0; mt < 2; mt++) {
        #pragma unroll
        for (int h = 0; h < 2; h++) {
            float m = -INFINITY, s = -INFINITY;
            int   id = 0;
            #pragma unroll
            for (int nt = 0; nt < 8; nt++) {
                #pragma unroll
                for (int e = 0; e < 2; e++) {
                    int   col = cbase + nt * 8 + e;
                    float v   = acc[mt][nt][h * 2 + e];
                    if (col >= NC) v = -INFINITY;
                    if (v > m) { s = m; m = v; id = col; }
                    else if (v > s) s = v;
                }
            }
            #pragma unroll
            for (int x = 1; x <= 2; x <<= 1) {
                float om = __shfl_xor_sync(0xffffffffu, m, x);
                int   oi = __shfl_xor_sync(0xffffffffu, id, x);
                float os = __shfl_xor_sync(0xffffffffu, s, x);
                comb(m, id, s, om, oi, os);
            }
            if ((lane & 3) == 0) {
                int rl = wm * 32 + mt * 16 + h * 8 + (lane >> 2);
                pm[wn * 128 + rl] = m;
                ps[wn * 128 + rl] = s;
                pi[wn * 128 + rl] = id;
            }
        }
    }
    __syncthreads();

    if (tid < 128) {
        float m = pm[tid];      int id = pi[tid];      float s = ps[tid];
        comb(m, id, s, pm[128 + tid], pi[128 + tid], ps[128 + tid]);
        size_t o = (size_t)(bm * BM + tid) * NBN + bn;
        g_pmax[o] = m; g_psnd[o] = s; g_pidx[o] = id;
    }
}

// ---------------- combine partials -> thr + write unflagged one-hot ---------
__global__ __launch_bounds__(256) void argmax_combine_kernel(float* __restrict__ out) {
    const int s = blockIdx.x * 256 + threadIdx.x;
    if (s >= NS) return;
    const size_t base = (size_t)s * NBN;
    float m = g_pmax[base];  int id = g_pidx[base];  float snd = g_psnd[base];
    #pragma unroll
    for (int p = 1; p < NBN; p++)
        comb(m, id, snd, g_pmax[base + p], g_pidx[base + p], g_psnd[base + p]);

    const float thr = m - MARGIN;
    if (snd >= thr) {
        g_thr[s] = thr;
        int p = atomicAdd(&g_refine_cnt, 1);
        g_refine_list[p] = s;
    } else {
        out[(size_t)s * NC + id] = 1.0f;   // no competitor within margin
    }
}

// ---------------- refine: 64-thr block/sample, float4 fp64 dot ---------------
// Scan via __half2 (8 independent loads/thread). Candidates split across the
// 2 warps; per-candidate dot uses float4 loads (32 LDG.128 instead of 128
// scalar LDG) with 8 fp64 accumulators. Deterministic final reduce.
__global__ __launch_bounds__(64, 8) void refine_small_kernel(
    const float* __restrict__ x, const float* __restrict__ means,
    float* __restrict__ out) {
    const int tid  = threadIdx.x;
    const int warp = tid >> 5;
    const int lane = tid & 31;

    __shared__ int    cnt;
    __shared__ int    cand[64];
    __shared__ double wv[2];
    __shared__ int    wc[2];

    const int total = g_refine_cnt;
    for (int r = blockIdx.x; r < total; r += gridDim.x) {
        const int    s    = g_refine_list[r];
        const float  thr  = g_thr[s];
        const __half2* srow2 =
            reinterpret_cast<const __half2*>(g_scores + (size_t)s * NCP);
        const float4* xr4 =
            reinterpret_cast<const float4*>(x + (size_t)s * ND);

        if (tid == 0) cnt = 0;
        __syncthreads();

        // batched scan: 8 independent half2 loads per thread (512 half2 total)
        float2 vv[8];
        #pragma unroll
        for (int i = 0; i < 8; i++)
            vv[i] = __half22float2(srow2[tid + i * 64]);
        #pragma unroll
        for (int i = 0; i < 8; i++) {
            int j = (tid + i * 64) * 2;
            if (j < NC && vv[i].x >= thr) {
                int p = atomicAdd(&cnt, 1); if (p < 64) cand[p] = j;
            }
            if (j + 1 < NC && vv[i].y >= thr) {
                int p = atomicAdd(&cnt, 1); if (p < 64) cand[p] = j + 1;
            }
        }
        __syncthreads();

        const int nc = (cnt < 64) ? cnt : 64;

        double bestv = -1e300;
        int    bestc = 1 << 30;
        for (int ci = warp; ci < nc; ci += 2) {
            const int cls = cand[ci];
            const float4* mr4 =
                reinterpret_cast<const float4*>(means + (size_t)cls * ND);
            double a0 = 0, a1 = 0, a2 = 0, a3 = 0, a4 = 0, a5 = 0, a6 = 0, a7 = 0;
            #pragma unroll
            for (int t = 0; t < 16; t += 2) {
                float4 xa = xr4[lane + t * 32];
                float4 ma = mr4[lane + t * 32];
                float4 xb = xr4[lane + (t + 1) * 32];
                float4 mb = mr4[lane + (t + 1) * 32];
                a0 += (double)xa.x * (double)ma.x;
                a1 += (double)xa.y * (double)ma.y;
                a2 += (double)xa.z * (double)ma.z;
                a3 += (double)xa.w * (double)ma.w;
                a4 += (double)xb.x * (double)mb.x;
                a5 += (double)xb.y * (double)mb.y;
                a6 += (double)xb.z * (double)mb.z;
                a7 += (double)xb.w * (double)mb.w;
            }
            double tot = ((a0 + a1) + (a2 + a3)) + ((a4 + a5) + (a6 + a7));
            #pragma unroll
            for (int o = 16; o > 0; o >>= 1)
                tot += __shfl_down_sync(0xffffffffu, tot, o);
            tot = __shfl_sync(0xffffffffu, tot, 0);
            if (tot > bestv || (tot == bestv && cls < bestc)) {
                bestv = tot; bestc = cls;
            }
        }
        if (lane == 0) { wv[warp] = bestv; wc[warp] = bestc; }
        __syncthreads();

        if (tid == 0) {
            double bv = wv[0]; int bc = wc[0];
            if (wv[1] > bv || (wv[1] == bv && wc[1] < bc)) { bv = wv[1]; bc = wc[1]; }
            out[(size_t)s * NC + bc] = 1.0f;
        }
        __syncthreads();
    }
}

// ---------------- launch ----------------------------------------------------
extern "C" void kernel_launch(void* const* d_in, const int* in_sizes, int n_in,
                              void* d_out, int out_size) {
    const float* x     = (const float*)d_in[0];
    const float* means = (const float*)d_in[1];
    float* out = (float*)d_out;

    cudaFuncSetAttribute(gemm_mma8_kernel,
                         cudaFuncAttributeMaxDynamicSharedMemorySize, SMEM_TOTAL);

    const int cvt_blocks = (int)((XCHUNKS + MCHUNKS) / 256);
    cvt_all_kernel<<<cvt_blocks, 256>>>(                          // launch 1
        reinterpret_cast<const float4*>(x),
        reinterpret_cast<const float4*>(means));
    gemm_mma8_kernel<<<dim3(NCP / BN, NS / BM), 256, SMEM_TOTAL>>>( // launch 2
        reinterpret_cast<float4*>(out));
    argmax_combine_kernel<<<NS / 256, 256>>>(out);                // launch 3
    refine_small_kernel<<<4096, 64>>>(x, means, out);             // launch 4 (ncu)
}